// round 2
// baseline (speedup 1.0000x reference)
#include <cuda_runtime.h>

#define N_BATCH 64
#define L_LEN   512
#define F_LEN   2048

// Spatial hash grid over B (fixed 2048 points, ~N(0,1) per coord)
#define G        32            // 32x32 cells
#define NCELL    (G * G)
#define CAP      64            // bin capacity (max expected occupancy ~7, Poisson tail << 1e-30)
#define LO      (-6.0f)
#define CELL     0.375f        // 12 / 32
#define INV_CELL 2.6666667f

__device__ int    g_count[NCELL];
__device__ float2 g_bins[NCELL * CAP];
__device__ int    g_scratch[N_BATCH];   // per-n running max of NN-dist (float bits, >= 0)
__device__ int    g_done;

__device__ __forceinline__ int cell_of(float v) {
    int c = __float2int_rd((v - LO) * INV_CELL);
    return min(max(c, 0), G - 1);
}

// One block: bin all B points into the grid; also reset scratch + done counter
// (runs first in every graph replay, so all mutable state is re-initialized).
__global__ __launch_bounds__(1024) void setup_kernel(const float* __restrict__ B) {
    const int t = threadIdx.x;
    g_count[t] = 0;
    if (t < N_BATCH) g_scratch[t] = 0;   // 0.0f; distances are >= 0
    if (t == 0) g_done = 0;
    __syncthreads();
    __threadfence();

    #pragma unroll
    for (int i = t; i < F_LEN; i += 1024) {
        const float bx = B[i];            // channel 0: B[0][0][i]
        const float by = B[F_LEN + i];    // channel 1: B[0][1][i]
        const int c = cell_of(by) * G + cell_of(bx);
        const int slot = atomicAdd(&g_count[c], 1);
        if (slot < CAP) g_bins[c * CAP + slot] = make_float2(bx, by);
    }
}

// One thread per (n,l) query: expanding square-ring NN search in Chebyshev
// metric (rings ARE the metric's iso-cells, so the prune bound is tight).
// Fused finish: last block computes sigmoid bump per n and writes out.
__global__ __launch_bounds__(128) void query_kernel(const float* __restrict__ A,
                                                    float* __restrict__ out) {
    const int tid = threadIdx.x;
    const int q = blockIdx.x * 128 + tid;              // 0..32767 == n*512 + l
    const int n = q >> 9;

    const float2 a = reinterpret_cast<const float2*>(A)[q];
    const int cx = cell_of(a.x);
    const int cy = cell_of(a.y);

    float best = 1e30f;

    for (int r = 0; r < G; ++r) {
        // Any point in a ring-r cell is >= (r-1)*CELL away (Chebyshev); valid
        // even for clamped queries (they are strictly farther from in-grid cells).
        if (best <= (float)(r - 1) * CELL) break;

        const int x0 = max(cx - r, 0), x1 = min(cx + r, G - 1);
        const int yl = cy - r,          yh = cy + r;
        const int y0 = max(yl, 0),      y1 = min(yh, G - 1);

        for (int y = y0; y <= y1; ++y) {
            const bool full_row = (y == yl) || (y == yh);
            const int rowbase = y * G;
            if (full_row) {
                for (int x = x0; x <= x1; ++x) {
                    const int c = rowbase + x;
                    const int cnt = min(g_count[c], CAP);
                    const float2* __restrict__ p = &g_bins[c * CAP];
                    for (int j = 0; j < cnt; ++j) {
                        const float2 b = p[j];
                        best = fminf(best, fmaxf(fabsf(a.x - b.x), fabsf(a.y - b.y)));
                    }
                }
            } else {
                if (cx - r >= 0) {
                    const int c = rowbase + cx - r;
                    const int cnt = min(g_count[c], CAP);
                    const float2* __restrict__ p = &g_bins[c * CAP];
                    for (int j = 0; j < cnt; ++j) {
                        const float2 b = p[j];
                        best = fminf(best, fmaxf(fabsf(a.x - b.x), fabsf(a.y - b.y)));
                    }
                }
                if (cx + r <= G - 1) {
                    const int c = rowbase + cx + r;
                    const int cnt = min(g_count[c], CAP);
                    const float2* __restrict__ p = &g_bins[c * CAP];
                    for (int j = 0; j < cnt; ++j) {
                        const float2 b = p[j];
                        best = fminf(best, fmaxf(fabsf(a.x - b.x), fabsf(a.y - b.y)));
                    }
                }
            }
        }
    }

    // max over l: warp reduce, then one atomic per warp (all q in a block share n)
    #pragma unroll
    for (int off = 16; off; off >>= 1)
        best = fmaxf(best, __shfl_xor_sync(0xffffffffu, best, off));
    if ((tid & 31) == 0)
        atomicMax(&g_scratch[n], __float_as_int(best));

    // fused finish: last block to arrive computes the 64 outputs
    __shared__ int s_last;
    __syncthreads();
    if (tid == 0) {
        __threadfence();                                   // release our atomicMax's
        s_last = (atomicAdd(&g_done, 1) == (int)gridDim.x - 1);
    }
    __syncthreads();
    if (s_last && tid < N_BATCH) {
        __threadfence();                                   // acquire others' atomicMax's
        const float x = __int_as_float(atomicMax(&g_scratch[tid], 0));  // coherent read
        const float s1 = 1.0f / (1.0f + expf(-10.0f * x));
        const float s2 = 1.0f / (1.0f + expf( 10.0f * x));
        out[tid] = s1 * s2;
    }
}

extern "C" void kernel_launch(void* const* d_in, const int* in_sizes, int n_in,
                              void* d_out, int out_size) {
    const float* A = (const float*)d_in[0];   // (64, 512, 2) fp32
    const float* B = (const float*)d_in[1];   // (1, 2, 2048) fp32
    float* out = (float*)d_out;               // (64, 1) fp32

    setup_kernel<<<1, 1024>>>(B);
    query_kernel<<<(N_BATCH * L_LEN) / 128, 128>>>(A, out);
}

// round 3
// speedup vs baseline: 1.0124x; 1.0124x over previous
#include <cuda_runtime.h>

#define N_BATCH 64
#define L_LEN   512
#define F_LEN   2048

// Spatial hash grid over B (fixed 2048 points, ~N(0,1) per coord)
#define G        32            // 32x32 cells
#define NCELL    (G * G)
#define CAP      64            // bin capacity (max expected occupancy ~7, Poisson tail << 1e-30)
#define LO      (-6.0f)
#define CELL     0.375f        // 12 / 32
#define INV_CELL 2.6666667f

__device__ int    g_count[NCELL];
__device__ float2 g_bins[NCELL * CAP];
__device__ int    g_scratch[N_BATCH];   // per-n running max of NN-dist (float bits, >= 0)
__device__ int    g_done;

__device__ __forceinline__ int cell_of(float v) {
    int c = __float2int_rd((v - LO) * INV_CELL);
    return min(max(c, 0), G - 1);
}

// One block: bin all B points into the grid; also reset scratch + done counter
// (runs first in every graph replay, so all mutable state is re-initialized).
__global__ __launch_bounds__(1024) void setup_kernel(const float* __restrict__ B) {
    const int t = threadIdx.x;
    g_count[t] = 0;
    if (t < N_BATCH) g_scratch[t] = 0;   // 0.0f; distances are >= 0
    if (t == 0) g_done = 0;
    __syncthreads();
    __threadfence();

    #pragma unroll
    for (int i = t; i < F_LEN; i += 1024) {
        const float bx = B[i];            // channel 0: B[0][0][i]
        const float by = B[F_LEN + i];    // channel 1: B[0][1][i]
        const int c = cell_of(by) * G + cell_of(bx);
        const int slot = atomicAdd(&g_count[c], 1);
        if (slot < CAP) g_bins[c * CAP + slot] = make_float2(bx, by);
    }
}

// One thread per (n,l) query: expanding square-ring NN search in Chebyshev
// metric (rings ARE the metric's iso-cells, so the prune bound is tight).
// Fused finish: last block computes sigmoid bump per n and writes out.
__global__ __launch_bounds__(128) void query_kernel(const float* __restrict__ A,
                                                    float* __restrict__ out) {
    const int tid = threadIdx.x;
    const int q = blockIdx.x * 128 + tid;              // 0..32767 == n*512 + l
    const int n = q >> 9;

    const float2 a = reinterpret_cast<const float2*>(A)[q];
    const int cx = cell_of(a.x);
    const int cy = cell_of(a.y);

    float best = 1e30f;

    for (int r = 0; r < G; ++r) {
        // Any point in a ring-r cell is >= (r-1)*CELL away (Chebyshev); valid
        // even for clamped queries (they are strictly farther from in-grid cells).
        if (best <= (float)(r - 1) * CELL) break;

        const int x0 = max(cx - r, 0), x1 = min(cx + r, G - 1);
        const int yl = cy - r,          yh = cy + r;
        const int y0 = max(yl, 0),      y1 = min(yh, G - 1);

        for (int y = y0; y <= y1; ++y) {
            const bool full_row = (y == yl) || (y == yh);
            const int rowbase = y * G;
            if (full_row) {
                for (int x = x0; x <= x1; ++x) {
                    const int c = rowbase + x;
                    const int cnt = min(g_count[c], CAP);
                    const float2* __restrict__ p = &g_bins[c * CAP];
                    for (int j = 0; j < cnt; ++j) {
                        const float2 b = p[j];
                        best = fminf(best, fmaxf(fabsf(a.x - b.x), fabsf(a.y - b.y)));
                    }
                }
            } else {
                if (cx - r >= 0) {
                    const int c = rowbase + cx - r;
                    const int cnt = min(g_count[c], CAP);
                    const float2* __restrict__ p = &g_bins[c * CAP];
                    for (int j = 0; j < cnt; ++j) {
                        const float2 b = p[j];
                        best = fminf(best, fmaxf(fabsf(a.x - b.x), fabsf(a.y - b.y)));
                    }
                }
                if (cx + r <= G - 1) {
                    const int c = rowbase + cx + r;
                    const int cnt = min(g_count[c], CAP);
                    const float2* __restrict__ p = &g_bins[c * CAP];
                    for (int j = 0; j < cnt; ++j) {
                        const float2 b = p[j];
                        best = fminf(best, fmaxf(fabsf(a.x - b.x), fabsf(a.y - b.y)));
                    }
                }
            }
        }
    }

    // max over l: warp reduce, then one atomic per warp (all q in a block share n)
    #pragma unroll
    for (int off = 16; off; off >>= 1)
        best = fmaxf(best, __shfl_xor_sync(0xffffffffu, best, off));
    if ((tid & 31) == 0)
        atomicMax(&g_scratch[n], __float_as_int(best));

    // fused finish: last block to arrive computes the 64 outputs
    __shared__ int s_last;
    __syncthreads();
    if (tid == 0) {
        __threadfence();                                   // release our atomicMax's
        s_last = (atomicAdd(&g_done, 1) == (int)gridDim.x - 1);
    }
    __syncthreads();
    if (s_last && tid < N_BATCH) {
        __threadfence();                                   // acquire others' atomicMax's
        const float x = __int_as_float(atomicMax(&g_scratch[tid], 0));  // coherent read
        const float s1 = 1.0f / (1.0f + expf(-10.0f * x));
        const float s2 = 1.0f / (1.0f + expf( 10.0f * x));
        out[tid] = s1 * s2;
    }
}

extern "C" void kernel_launch(void* const* d_in, const int* in_sizes, int n_in,
                              void* d_out, int out_size) {
    const float* A = (const float*)d_in[0];   // (64, 512, 2) fp32
    const float* B = (const float*)d_in[1];   // (1, 2, 2048) fp32
    float* out = (float*)d_out;               // (64, 1) fp32

    setup_kernel<<<1, 1024>>>(B);
    query_kernel<<<(N_BATCH * L_LEN) / 128, 128>>>(A, out);
}